// round 1
// baseline (speedup 1.0000x reference)
#include <cuda_runtime.h>

#define NN 100000
#define NE_CAP 1700000
#define NB_SCAN 98   /* ceil(100000/1024) */

// ---- scratch (device globals: allocation-free) ----
__device__ __align__(16) float g_Z[NN * 64];
__device__ __align__(16) float g_H[NN * 64];
__device__ float g_onorm[NN];
__device__ float g_inorm[NN];
__device__ int   g_cout[NN];
__device__ int   g_cin[NN];
__device__ int   g_ptr[NN + 1];
__device__ int   g_fill[NN];
__device__ int   g_csr[NE_CAP];
__device__ int   g_part[NB_SCAN];

// ---------------- graph preprocessing ----------------
__global__ void k_init(int* cout, int* cin) {
    int i = blockIdx.x * blockDim.x + threadIdx.x;
    if (i < NN) { cout[i] = 0; cin[i] = 0; }
}

__global__ void k_degree(const int* __restrict__ src, const int* __restrict__ dst,
                         int* cout, int* cin, int E) {
    int i = blockIdx.x * blockDim.x + threadIdx.x;
    if (i < E) {
        atomicAdd(&cout[src[i]], 1);
        atomicAdd(&cin[dst[i]], 1);
    }
}

__global__ void k_norm(const int* __restrict__ cout, const int* __restrict__ cin,
                       float* onorm, float* inorm) {
    int i = blockIdx.x * blockDim.x + threadIdx.x;
    if (i < NN) {
        // +1 for the self loop; degree always >= 1 so no max() needed
        onorm[i] = rsqrtf((float)(cout[i] + 1));
        inorm[i] = rsqrtf((float)(cin[i] + 1));
    }
}

__global__ void k_scan_partial(const int* __restrict__ cin, int* part) {
    __shared__ int wsum[8];
    int b = blockIdx.x, t = threadIdx.x;
    int base = b * 1024 + t * 4;
    int s = 0;
#pragma unroll
    for (int j = 0; j < 4; j++) { int i = base + j; if (i < NN) s += cin[i]; }
    for (int o = 16; o > 0; o >>= 1) s += __shfl_down_sync(0xffffffffu, s, o);
    if ((t & 31) == 0) wsum[t >> 5] = s;
    __syncthreads();
    if (t == 0) {
        int tot = 0;
        for (int w = 0; w < 8; w++) tot += wsum[w];
        part[b] = tot;
    }
}

__global__ void k_scan_offsets(int* part, int* ptr) {
    int run = 0;
    for (int b = 0; b < NB_SCAN; b++) { int v = part[b]; part[b] = run; run += v; }
    ptr[NN] = run;
}

__global__ void k_scan_write(const int* __restrict__ cin, const int* __restrict__ part,
                             int* ptr, int* fill) {
    __shared__ int wexc[8];
    int b = blockIdx.x, t = threadIdx.x;
    int lane = t & 31, warp = t >> 5;
    int base = b * 1024 + t * 4;
    int v[4];
#pragma unroll
    for (int j = 0; j < 4; j++) { int i = base + j; v[j] = (i < NN) ? cin[i] : 0; }
    int s = v[0] + v[1] + v[2] + v[3];
    int inc = s;
    for (int o = 1; o < 32; o <<= 1) {
        int u = __shfl_up_sync(0xffffffffu, inc, o);
        if (lane >= o) inc += u;
    }
    if (lane == 31) wexc[warp] = inc;
    __syncthreads();
    if (warp == 0) {
        int w = (lane < 8) ? wexc[lane] : 0;
        int winc = w;
        for (int o = 1; o < 8; o <<= 1) {
            int u = __shfl_up_sync(0xffffffffu, winc, o);
            if (lane >= o) winc += u;
        }
        if (lane < 8) wexc[lane] = winc - w;  // exclusive warp offsets
    }
    __syncthreads();
    int pos = part[b] + wexc[warp] + (inc - s);
#pragma unroll
    for (int j = 0; j < 4; j++) {
        int i = base + j;
        if (i < NN) { ptr[i] = pos; fill[i] = pos; }
        pos += v[j];
    }
}

__global__ void k_fill(const int* __restrict__ src, const int* __restrict__ dst,
                       int* fill, int* csr, int E) {
    int i = blockIdx.x * blockDim.x + threadIdx.x;
    if (i < E) {
        int p = atomicAdd(&fill[dst[i]], 1);
        csr[p] = src[i];
    }
}

// ---------------- dense GEMM: Z = out_norm .* (A @ W), A is [NN,K], W is [K,64] ----------------
template <int K>
__global__ void __launch_bounds__(128) k_gemm(const float* __restrict__ A,
                                              const float* __restrict__ W,
                                              const float* __restrict__ onorm,
                                              float* __restrict__ Z) {
    __shared__ float As[16][128];
    __shared__ float Bs[16][64];
    const int tid = threadIdx.x;           // 128 threads
    const int tr = tid >> 3, tc = tid & 7; // 16 x 8 thread grid, 8x8 per thread
    const int rowBase = blockIdx.x * 128;

    float acc[8][8];
#pragma unroll
    for (int i = 0; i < 8; i++)
#pragma unroll
        for (int j = 0; j < 8; j++) acc[i][j] = 0.f;

    for (int k0 = 0; k0 < K; k0 += 16) {
        // A tile: thread loads full 16-wide slice of its row, stores transposed
        int r = rowBase + tid;
        if (r < NN) {
            const float4* ap = reinterpret_cast<const float4*>(A + (long)r * K + k0);
            float4 a0 = ap[0], a1 = ap[1], a2 = ap[2], a3 = ap[3];
            As[0][tid] = a0.x;  As[1][tid] = a0.y;  As[2][tid] = a0.z;  As[3][tid] = a0.w;
            As[4][tid] = a1.x;  As[5][tid] = a1.y;  As[6][tid] = a1.z;  As[7][tid] = a1.w;
            As[8][tid] = a2.x;  As[9][tid] = a2.y;  As[10][tid] = a2.z; As[11][tid] = a2.w;
            As[12][tid] = a3.x; As[13][tid] = a3.y; As[14][tid] = a3.z; As[15][tid] = a3.w;
        } else {
#pragma unroll
            for (int k = 0; k < 16; k++) As[k][tid] = 0.f;
        }
        // B tile: contiguous 1024 floats (full 64-wide), 2 x float4 per thread
        {
            const float4* bp = reinterpret_cast<const float4*>(W + k0 * 64);
            float4 w0 = bp[tid * 2], w1 = bp[tid * 2 + 1];
            float4* bs = reinterpret_cast<float4*>(&Bs[0][0]);
            bs[tid * 2] = w0;
            bs[tid * 2 + 1] = w1;
        }
        __syncthreads();
#pragma unroll
        for (int k = 0; k < 16; k++) {
            float a[8], bb[8];
            *(float4*)&a[0]  = *(const float4*)&As[k][tr * 8];
            *(float4*)&a[4]  = *(const float4*)&As[k][tr * 8 + 4];
            *(float4*)&bb[0] = *(const float4*)&Bs[k][tc * 8];
            *(float4*)&bb[4] = *(const float4*)&Bs[k][tc * 8 + 4];
#pragma unroll
            for (int i = 0; i < 8; i++)
#pragma unroll
                for (int j = 0; j < 8; j++) acc[i][j] += a[i] * bb[j];
        }
        __syncthreads();
    }
#pragma unroll
    for (int i = 0; i < 8; i++) {
        int r = rowBase + tr * 8 + i;
        if (r < NN) {
            float sc = onorm[r];
            float4 o0 = make_float4(acc[i][0] * sc, acc[i][1] * sc, acc[i][2] * sc, acc[i][3] * sc);
            float4 o1 = make_float4(acc[i][4] * sc, acc[i][5] * sc, acc[i][6] * sc, acc[i][7] * sc);
            float4* zp = reinterpret_cast<float4*>(Z + (long)r * 64 + tc * 8);
            zp[0] = o0;
            zp[1] = o1;
        }
    }
}

// ---------------- SpMM gather: Hout[v] = inorm[v]*(sum_{e:dst=v} Z[src_e] + Z[v]) + b ----------------
__global__ void __launch_bounds__(256) k_gather(const float* __restrict__ Z,
                                                const int* __restrict__ ptr,
                                                const int* __restrict__ csr,
                                                const float* __restrict__ inorm,
                                                const float* __restrict__ bias,
                                                float* __restrict__ Hout) {
    int warp = (blockIdx.x * blockDim.x + threadIdx.x) >> 5;
    int lane = threadIdx.x & 31;
    if (warp >= NN) return;
    int v = warp;
    int beg = ptr[v], end = ptr[v + 1];
    // self loop contribution
    float acc0 = Z[(long)v * 64 + lane];
    float acc1 = Z[(long)v * 64 + 32 + lane];
    for (int e = beg; e < end; e += 32) {
        int nrem = end - e;
        int s = (lane < nrem) ? csr[e + lane] : 0;
        int cnt = nrem < 32 ? nrem : 32;
        for (int j = 0; j < cnt; j++) {
            int sj = __shfl_sync(0xffffffffu, s, j);
            acc0 += Z[(long)sj * 64 + lane];
            acc1 += Z[(long)sj * 64 + 32 + lane];
        }
    }
    float ni = inorm[v];
    Hout[(long)v * 64 + lane]      = ni * acc0 + bias[lane];
    Hout[(long)v * 64 + 32 + lane] = ni * acc1 + bias[32 + lane];
}

__global__ void k_ids(const int* __restrict__ ids, float* out, int n) {
    int i = blockIdx.x * blockDim.x + threadIdx.x;
    if (i < n) out[NN * 64 + i] = (float)ids[i];
}

// ---------------- launch ----------------
extern "C" void kernel_launch(void* const* d_in, const int* in_sizes, int n_in,
                              void* d_out, int out_size) {
    const float* h   = (const float*)d_in[0];
    const int*   src = (const int*)d_in[1];
    const int*   dst = (const int*)d_in[2];
    const int*   ids = (const int*)d_in[3];
    const float* W0  = (const float*)d_in[4];
    const float* b0  = (const float*)d_in[5];
    const float* W1  = (const float*)d_in[6];
    const float* b1  = (const float*)d_in[7];
    const float* W2  = (const float*)d_in[8];
    const float* b2  = (const float*)d_in[9];
    float* out = (float*)d_out;
    int E = in_sizes[1];

    float *pZ, *pH, *pon, *pin;
    int *pcout, *pcin, *pptr, *pfill, *pcsr, *ppart;
    cudaGetSymbolAddress((void**)&pZ, g_Z);
    cudaGetSymbolAddress((void**)&pH, g_H);
    cudaGetSymbolAddress((void**)&pon, g_onorm);
    cudaGetSymbolAddress((void**)&pin, g_inorm);
    cudaGetSymbolAddress((void**)&pcout, g_cout);
    cudaGetSymbolAddress((void**)&pcin, g_cin);
    cudaGetSymbolAddress((void**)&pptr, g_ptr);
    cudaGetSymbolAddress((void**)&pfill, g_fill);
    cudaGetSymbolAddress((void**)&pcsr, g_csr);
    cudaGetSymbolAddress((void**)&ppart, g_part);

    k_init<<<(NN + 255) / 256, 256>>>(pcout, pcin);
    k_degree<<<(E + 255) / 256, 256>>>(src, dst, pcout, pcin, E);
    k_norm<<<(NN + 255) / 256, 256>>>(pcout, pcin, pon, pin);
    k_scan_partial<<<NB_SCAN, 256>>>(pcin, ppart);
    k_scan_offsets<<<1, 1>>>(ppart, pptr);
    k_scan_write<<<NB_SCAN, 256>>>(pcin, ppart, pptr, pfill);
    k_fill<<<(E + 255) / 256, 256>>>(src, dst, pfill, pcsr, E);

    const int gblk = (NN + 127) / 128;
    const int wblk = (NN * 32 + 255) / 256;

    k_gemm<128><<<gblk, 128>>>(h, W0, pon, pZ);
    k_gather<<<wblk, 256>>>(pZ, pptr, pcsr, pin, b0, pH);
    k_gemm<64><<<gblk, 128>>>(pH, W1, pon, pZ);
    k_gather<<<wblk, 256>>>(pZ, pptr, pcsr, pin, b1, pH);
    k_gemm<64><<<gblk, 128>>>(pH, W2, pon, pZ);
    k_gather<<<wblk, 256>>>(pZ, pptr, pcsr, pin, b2, out);

    if (out_size > NN * 64) {
        int nid = out_size - NN * 64;
        if (nid > in_sizes[3]) nid = in_sizes[3];
        k_ids<<<(nid + 255) / 256, 256>>>(ids, out, nid);
    }
}

// round 2
// speedup vs baseline: 1.6412x; 1.6412x over previous
#include <cuda_runtime.h>

#define NN 100000
#define NE_CAP 1700000
#define NB_SCAN 98   /* ceil(100000/1024) */

// ---- scratch (device globals: allocation-free) ----
__device__ __align__(16) float g_Z[NN * 64];
__device__ __align__(16) float g_H[NN * 64];
__device__ float g_onorm[NN];
__device__ float g_inorm[NN];
__device__ int   g_cout[NN];
__device__ int   g_cin[NN];
__device__ int   g_ptr[NN + 1];
__device__ int   g_fill[NN];
__device__ int   g_csr[NE_CAP];
__device__ int   g_part[NB_SCAN];

// ---------------- graph preprocessing ----------------
__global__ void k_init(int* cout, int* cin) {
    int i = blockIdx.x * blockDim.x + threadIdx.x;
    if (i < NN) { cout[i] = 0; cin[i] = 0; }
}

__global__ void k_degree(const int* __restrict__ src, const int* __restrict__ dst,
                         int* cout, int* cin, int E) {
    int i = blockIdx.x * blockDim.x + threadIdx.x;
    if (i < E) {
        atomicAdd(&cout[src[i]], 1);
        atomicAdd(&cin[dst[i]], 1);
    }
}

__global__ void k_norm(const int* __restrict__ cout, const int* __restrict__ cin,
                       float* onorm, float* inorm) {
    int i = blockIdx.x * blockDim.x + threadIdx.x;
    if (i < NN) {
        // +1 for the self loop; degree always >= 1 so no max() needed
        onorm[i] = rsqrtf((float)(cout[i] + 1));
        inorm[i] = rsqrtf((float)(cin[i] + 1));
    }
}

__global__ void k_scan_partial(const int* __restrict__ cin, int* part) {
    __shared__ int wsum[8];
    int b = blockIdx.x, t = threadIdx.x;
    int base = b * 1024 + t * 4;
    int s = 0;
#pragma unroll
    for (int j = 0; j < 4; j++) { int i = base + j; if (i < NN) s += cin[i]; }
    for (int o = 16; o > 0; o >>= 1) s += __shfl_down_sync(0xffffffffu, s, o);
    if ((t & 31) == 0) wsum[t >> 5] = s;
    __syncthreads();
    if (t == 0) {
        int tot = 0;
        for (int w = 0; w < 8; w++) tot += wsum[w];
        part[b] = tot;
    }
}

__global__ void k_scan_offsets(int* part, int* ptr) {
    int run = 0;
    for (int b = 0; b < NB_SCAN; b++) { int v = part[b]; part[b] = run; run += v; }
    ptr[NN] = run;
}

__global__ void k_scan_write(const int* __restrict__ cin, const int* __restrict__ part,
                             int* ptr, int* fill) {
    __shared__ int wexc[8];
    int b = blockIdx.x, t = threadIdx.x;
    int lane = t & 31, warp = t >> 5;
    int base = b * 1024 + t * 4;
    int v[4];
#pragma unroll
    for (int j = 0; j < 4; j++) { int i = base + j; v[j] = (i < NN) ? cin[i] : 0; }
    int s = v[0] + v[1] + v[2] + v[3];
    int inc = s;
    for (int o = 1; o < 32; o <<= 1) {
        int u = __shfl_up_sync(0xffffffffu, inc, o);
        if (lane >= o) inc += u;
    }
    if (lane == 31) wexc[warp] = inc;
    __syncthreads();
    if (warp == 0) {
        int w = (lane < 8) ? wexc[lane] : 0;
        int winc = w;
        for (int o = 1; o < 8; o <<= 1) {
            int u = __shfl_up_sync(0xffffffffu, winc, o);
            if (lane >= o) winc += u;
        }
        if (lane < 8) wexc[lane] = winc - w;  // exclusive warp offsets
    }
    __syncthreads();
    int pos = part[b] + wexc[warp] + (inc - s);
#pragma unroll
    for (int j = 0; j < 4; j++) {
        int i = base + j;
        if (i < NN) { ptr[i] = pos; fill[i] = pos; }
        pos += v[j];
    }
}

__global__ void k_fill(const int* __restrict__ src, const int* __restrict__ dst,
                       int* fill, int* csr, int E) {
    int i = blockIdx.x * blockDim.x + threadIdx.x;
    if (i < E) {
        int p = atomicAdd(&fill[dst[i]], 1);
        csr[p] = src[i];
    }
}

// ---------------- dense GEMM: Z = out_norm .* (A @ W), A is [NN,K], W is [K,64] ----------------
// Whole W lives in smem (one load + one sync). A streams from GMEM through a
// register double buffer; lanes sharing tr broadcast-load the same A addresses.
template <int K>
__global__ void __launch_bounds__(128, 2) k_gemm(const float* __restrict__ A,
                                                 const float* __restrict__ W,
                                                 const float* __restrict__ onorm,
                                                 float* __restrict__ Z) {
    __shared__ float Bs[K * 64];
    const int tid = threadIdx.x;
    {
        const float4* wp = reinterpret_cast<const float4*>(W);
        float4* bs = reinterpret_cast<float4*>(Bs);
#pragma unroll
        for (int i = 0; i < (K * 16) / 128; i++)
            bs[tid + i * 128] = wp[tid + i * 128];
    }
    __syncthreads();

    const int tr = tid >> 3, tc = tid & 7;
    const int row0 = blockIdx.x * 128 + tr * 8;

    const float* ap[8];
#pragma unroll
    for (int i = 0; i < 8; i++) {
        int r = row0 + i;
        if (r > NN - 1) r = NN - 1;   // clamp: loads stay valid, stores guarded later
        ap[i] = A + (long)r * K;
    }

    float acc[8][8];
#pragma unroll
    for (int i = 0; i < 8; i++)
#pragma unroll
        for (int j = 0; j < 8; j++) acc[i][j] = 0.f;

    float4 buf0[8], buf1[8];
#pragma unroll
    for (int i = 0; i < 8; i++) buf0[i] = *reinterpret_cast<const float4*>(ap[i]);

#pragma unroll 2
    for (int k0 = 0; k0 < K; k0 += 8) {
        // prefetch second half of this 8-chunk
#pragma unroll
        for (int i = 0; i < 8; i++)
            buf1[i] = *reinterpret_cast<const float4*>(ap[i] + k0 + 4);
        // compute k0..k0+3 from buf0
#pragma unroll
        for (int kk = 0; kk < 4; kk++) {
            float4 w0 = *reinterpret_cast<const float4*>(&Bs[(k0 + kk) * 64 + tc * 8]);
            float4 w1 = *reinterpret_cast<const float4*>(&Bs[(k0 + kk) * 64 + tc * 8 + 4]);
            float wv[8] = {w0.x, w0.y, w0.z, w0.w, w1.x, w1.y, w1.z, w1.w};
#pragma unroll
            for (int i = 0; i < 8; i++) {
                float a = (kk == 0) ? buf0[i].x : (kk == 1) ? buf0[i].y
                        : (kk == 2) ? buf0[i].z : buf0[i].w;
#pragma unroll
                for (int j = 0; j < 8; j++) acc[i][j] += a * wv[j];
            }
        }
        // prefetch first half of next 8-chunk
        if (k0 + 8 < K) {
#pragma unroll
            for (int i = 0; i < 8; i++)
                buf0[i] = *reinterpret_cast<const float4*>(ap[i] + k0 + 8);
        }
        // compute k0+4..k0+7 from buf1
#pragma unroll
        for (int kk = 0; kk < 4; kk++) {
            float4 w0 = *reinterpret_cast<const float4*>(&Bs[(k0 + 4 + kk) * 64 + tc * 8]);
            float4 w1 = *reinterpret_cast<const float4*>(&Bs[(k0 + 4 + kk) * 64 + tc * 8 + 4]);
            float wv[8] = {w0.x, w0.y, w0.z, w0.w, w1.x, w1.y, w1.z, w1.w};
#pragma unroll
            for (int i = 0; i < 8; i++) {
                float a = (kk == 0) ? buf1[i].x : (kk == 1) ? buf1[i].y
                        : (kk == 2) ? buf1[i].z : buf1[i].w;
#pragma unroll
                for (int j = 0; j < 8; j++) acc[i][j] += a * wv[j];
            }
        }
    }

#pragma unroll
    for (int i = 0; i < 8; i++) {
        int r = row0 + i;
        if (r < NN) {
            float sc = onorm[r];
            float4 o0 = make_float4(acc[i][0] * sc, acc[i][1] * sc, acc[i][2] * sc, acc[i][3] * sc);
            float4 o1 = make_float4(acc[i][4] * sc, acc[i][5] * sc, acc[i][6] * sc, acc[i][7] * sc);
            float4* zp = reinterpret_cast<float4*>(Z + (long)r * 64 + tc * 8);
            zp[0] = o0;
            zp[1] = o1;
        }
    }
}

// ---------------- SpMM gather: Hout[v] = inorm[v]*(sum_{e:dst=v} Z[src_e] + Z[v]) + b ----------------
__global__ void __launch_bounds__(256) k_gather(const float* __restrict__ Z,
                                                const int* __restrict__ ptr,
                                                const int* __restrict__ csr,
                                                const float* __restrict__ inorm,
                                                const float* __restrict__ bias,
                                                float* __restrict__ Hout) {
    int warp = (blockIdx.x * blockDim.x + threadIdx.x) >> 5;
    int lane = threadIdx.x & 31;
    if (warp >= NN) return;
    int v = warp;
    int beg = ptr[v], end = ptr[v + 1];
    // self loop contribution
    float acc0 = Z[(long)v * 64 + lane];
    float acc1 = Z[(long)v * 64 + 32 + lane];
    for (int e = beg; e < end; e += 32) {
        int nrem = end - e;
        int s = (lane < nrem) ? csr[e + lane] : 0;
        int cnt = nrem < 32 ? nrem : 32;
        for (int j = 0; j < cnt; j++) {
            int sj = __shfl_sync(0xffffffffu, s, j);
            acc0 += Z[(long)sj * 64 + lane];
            acc1 += Z[(long)sj * 64 + 32 + lane];
        }
    }
    float ni = inorm[v];
    Hout[(long)v * 64 + lane]      = ni * acc0 + bias[lane];
    Hout[(long)v * 64 + 32 + lane] = ni * acc1 + bias[32 + lane];
}

__global__ void k_ids(const int* __restrict__ ids, float* out, int n) {
    int i = blockIdx.x * blockDim.x + threadIdx.x;
    if (i < n) out[NN * 64 + i] = (float)ids[i];
}

// ---------------- launch ----------------
extern "C" void kernel_launch(void* const* d_in, const int* in_sizes, int n_in,
                              void* d_out, int out_size) {
    const float* h   = (const float*)d_in[0];
    const int*   src = (const int*)d_in[1];
    const int*   dst = (const int*)d_in[2];
    const int*   ids = (const int*)d_in[3];
    const float* W0  = (const float*)d_in[4];
    const float* b0  = (const float*)d_in[5];
    const float* W1  = (const float*)d_in[6];
    const float* b1  = (const float*)d_in[7];
    const float* W2  = (const float*)d_in[8];
    const float* b2  = (const float*)d_in[9];
    float* out = (float*)d_out;
    int E = in_sizes[1];

    float *pZ, *pH, *pon, *pin;
    int *pcout, *pcin, *pptr, *pfill, *pcsr, *ppart;
    cudaGetSymbolAddress((void**)&pZ, g_Z);
    cudaGetSymbolAddress((void**)&pH, g_H);
    cudaGetSymbolAddress((void**)&pon, g_onorm);
    cudaGetSymbolAddress((void**)&pin, g_inorm);
    cudaGetSymbolAddress((void**)&pcout, g_cout);
    cudaGetSymbolAddress((void**)&pcin, g_cin);
    cudaGetSymbolAddress((void**)&pptr, g_ptr);
    cudaGetSymbolAddress((void**)&pfill, g_fill);
    cudaGetSymbolAddress((void**)&pcsr, g_csr);
    cudaGetSymbolAddress((void**)&ppart, g_part);

    k_init<<<(NN + 255) / 256, 256>>>(pcout, pcin);
    k_degree<<<(E + 255) / 256, 256>>>(src, dst, pcout, pcin, E);
    k_norm<<<(NN + 255) / 256, 256>>>(pcout, pcin, pon, pin);
    k_scan_partial<<<NB_SCAN, 256>>>(pcin, ppart);
    k_scan_offsets<<<1, 1>>>(ppart, pptr);
    k_scan_write<<<NB_SCAN, 256>>>(pcin, ppart, pptr, pfill);
    k_fill<<<(E + 255) / 256, 256>>>(src, dst, pfill, pcsr, E);

    const int gblk = (NN + 127) / 128;
    const int wblk = (NN * 32 + 255) / 256;

    k_gemm<128><<<gblk, 128>>>(h, W0, pon, pZ);
    k_gather<<<wblk, 256>>>(pZ, pptr, pcsr, pin, b0, pH);
    k_gemm<64><<<gblk, 128>>>(pH, W1, pon, pZ);
    k_gather<<<wblk, 256>>>(pZ, pptr, pcsr, pin, b1, pH);
    k_gemm<64><<<gblk, 128>>>(pH, W2, pon, pZ);
    k_gather<<<wblk, 256>>>(pZ, pptr, pcsr, pin, b2, out);

    if (out_size > NN * 64) {
        int nid = out_size - NN * 64;
        if (nid > in_sizes[3]) nid = in_sizes[3];
        k_ids<<<(nid + 255) / 256, 256>>>(ids, out, nid);
    }
}